// round 14
// baseline (speedup 1.0000x reference)
#include <cuda_runtime.h>
#include <cuda_bf16.h>
#include <math.h>
#include <stdint.h>

static constexpr int kT = 512;
static constexpr int kB = 16;
static constexpr int kD = 2048;
static constexpr int kBD = kB * kD;          // 32768
static constexpr int kM = kT * kB;           // 8192 rows in big GEMMs

// Scratch (device globals; no allocation allowed)
__device__ float g_Xp[kT * kBD];                 // X @ Wx   [T*B, D]
__device__ __nv_bfloat16 g_Hs0[(kT + 1) * kBD]; // h bf16 hi; slot t = h_{t-1}
__device__ __nv_bfloat16 g_Hs1[(kT + 1) * kBD]; // h bf16 lo
__device__ __nv_bfloat16 g_Xs0[kM * kD];         // x bf16 hi
__device__ __nv_bfloat16 g_Xs1[kM * kD];         // x bf16 lo
__device__ __nv_bfloat16 g_WxT0[kD * kD];        // W^T splits, [N][K]
__device__ __nv_bfloat16 g_WxT1[kD * kD];
__device__ __nv_bfloat16 g_WoT0[kD * kD];
__device__ __nv_bfloat16 g_WoT1[kD * kD];
__device__ __nv_bfloat16 g_WhT0[kD * kD];
__device__ __nv_bfloat16 g_WhT1[kD * kD];
// 8 group epoch counters (one per 16-CTA column group), 128B apart
__device__ unsigned g_counts[8 * 32];

// ===========================================================================
// PTX helpers — base sm_103 ISA only (no 'a'-gated features)
// ===========================================================================
__device__ __forceinline__ uint32_t smem_u32(const void* p) {
    uint32_t a;
    asm("{ .reg .u64 t; cvta.to.shared.u64 t, %1; cvt.u32.u64 %0, t; }"
        : "=r"(a) : "l"(p));
    return a;
}
#define CP_ASYNC16(dst, src) \
    asm volatile("cp.async.cg.shared.global [%0], [%1], 16;" \
                 :: "r"(dst), "l"(src) : "memory")
#define CP_COMMIT() asm volatile("cp.async.commit_group;" ::: "memory")
#define CP_WAIT1()  asm volatile("cp.async.wait_group 1;" ::: "memory")
#define CP_WAIT0()  asm volatile("cp.async.wait_group 0;" ::: "memory")

#define LDMATRIX_X4(r, addr) \
    asm volatile("ldmatrix.sync.aligned.m8n8.x4.shared.b16 {%0,%1,%2,%3}, [%4];" \
        : "=r"((r)[0]), "=r"((r)[1]), "=r"((r)[2]), "=r"((r)[3]) : "r"(addr))

#define MMA16816(d, a, b0, b1) \
    asm volatile("mma.sync.aligned.m16n8k16.row.col.f32.bf16.bf16.f32 " \
        "{%0,%1,%2,%3}, {%4,%5,%6,%7}, {%8,%9}, {%0,%1,%2,%3};" \
        : "+f"((d)[0]), "+f"((d)[1]), "+f"((d)[2]), "+f"((d)[3]) \
        : "r"((a)[0]), "r"((a)[1]), "r"((a)[2]), "r"((a)[3]), "r"(b0), "r"(b1))

#define SMEM_SWIZZLE_128B(x) ((x) ^ (((x) >> 3) & 0x70))
#define SMEM_SWIZZLE_64B(x)  ((x) ^ (((x) >> 3) & 0x30))

__device__ __forceinline__ unsigned pack_bf2(__nv_bfloat16 a, __nv_bfloat16 b) {
    __nv_bfloat162 h = __halves2bfloat162(a, b);
    return *reinterpret_cast<unsigned*>(&h);
}

// ===========================================================================
// Fused prep: transpose+split ALL THREE weights in one launch (grid.z picks
// the matrix); also zeroes the 8 group counters (stream-ordered before scan).
// ===========================================================================
__global__ void prep_wT3_kernel(const float* __restrict__ Wx,
                                const float* __restrict__ Wh,
                                const float* __restrict__ Wo,
                                __nv_bfloat16* __restrict__ WxT0,
                                __nv_bfloat16* __restrict__ WxT1,
                                __nv_bfloat16* __restrict__ WhT0,
                                __nv_bfloat16* __restrict__ WhT1,
                                __nv_bfloat16* __restrict__ WoT0,
                                __nv_bfloat16* __restrict__ WoT1)
{
    const float* W;
    __nv_bfloat16 *T0, *T1;
    if (blockIdx.z == 0)      { W = Wx; T0 = WxT0; T1 = WxT1; }
    else if (blockIdx.z == 1) { W = Wh; T0 = WhT0; T1 = WhT1; }
    else                      { W = Wo; T0 = WoT0; T1 = WoT1; }

    __shared__ float tile[32][33];
    const int n0 = blockIdx.x * 32, k0 = blockIdx.y * 32;
    const int tx = threadIdx.x, ty = threadIdx.y;
    tile[ty][tx] = W[(size_t)(k0 + ty) * kD + n0 + tx];
    __syncthreads();
    float v = tile[tx][ty];                       // = W[k0+tx][n0+ty]
    __nv_bfloat16 b0 = __float2bfloat16_rn(v);
    float r = v - __bfloat162float(b0);
    __nv_bfloat16 b1 = __float2bfloat16_rn(r);
    size_t o = (size_t)(n0 + ty) * kD + k0 + tx;  // T[n][k]
    T0[o] = b0;
    T1[o] = b1;

    if (blockIdx.x == 0 && blockIdx.y == 0 && blockIdx.z == 0 &&
        ty == 0 && tx < 8)
        g_counts[tx * 32] = 0;                    // fold in barrier reset
}

// Fused fp32 -> bf16 hi/lo split for x AND h0 in one launch.
__global__ void split2_kernel(const float* __restrict__ x,
                              __nv_bfloat16* __restrict__ xo0,
                              __nv_bfloat16* __restrict__ xo1, int n4x,
                              const float* __restrict__ h,
                              __nv_bfloat16* __restrict__ ho0,
                              __nv_bfloat16* __restrict__ ho1, int n4h)
{
    int i = blockIdx.x * blockDim.x + threadIdx.x;
    const float* in;
    __nv_bfloat16 *o0, *o1;
    int idx;
    if (i < n4x) { in = x; o0 = xo0; o1 = xo1; idx = i; }
    else {
        idx = i - n4x;
        if (idx >= n4h) return;
        in = h; o0 = ho0; o1 = ho1;
    }
    float4 v = __ldg(reinterpret_cast<const float4*>(in) + idx);
    __nv_bfloat16 hx = __float2bfloat16_rn(v.x);
    __nv_bfloat16 hy = __float2bfloat16_rn(v.y);
    __nv_bfloat16 hz = __float2bfloat16_rn(v.z);
    __nv_bfloat16 hw = __float2bfloat16_rn(v.w);
    __nv_bfloat16 lx = __float2bfloat16_rn(v.x - __bfloat162float(hx));
    __nv_bfloat16 ly = __float2bfloat16_rn(v.y - __bfloat162float(hy));
    __nv_bfloat16 lz = __float2bfloat16_rn(v.z - __bfloat162float(hz));
    __nv_bfloat16 lw = __float2bfloat16_rn(v.w - __bfloat162float(hw));
    uint2 p0 = make_uint2(pack_bf2(hx, hy), pack_bf2(hz, hw));
    uint2 p1 = make_uint2(pack_bf2(lx, ly), pack_bf2(lz, lw));
    reinterpret_cast<uint2*>(o0)[idx] = p0;
    reinterpret_cast<uint2*>(o1)[idx] = p1;
}

// ===========================================================================
// HMMA bf16x3 GEMM v6 (unchanged from R12/R13)
// ===========================================================================
__global__ __launch_bounds__(256, 2) void gemm_bf16_kernel(
    const __nv_bfloat16* __restrict__ A0, const __nv_bfloat16* __restrict__ A1,
    const __nv_bfloat16* __restrict__ B0, const __nv_bfloat16* __restrict__ B1,
    float* __restrict__ C)
{
    extern __shared__ char sm[];   // [3 stages][4 tiles][8192B]; tile=[128][32] bf16

    const int tid = threadIdx.x;
    const int wid = tid >> 5;
    const int lane = tid & 31;
    const int m0 = blockIdx.y * 128, n0 = blockIdx.x * 128;
    const int wm = (wid & 3) * 32;
    const int wn = (wid >> 2) * 64;

    auto stage = [&](int buf, int c) {
        const int k0 = c * 32;
        char* base = sm + buf * 32768;
        const __nv_bfloat16* srcs[4] = {
            A0 + (size_t)m0 * kD + k0, A1 + (size_t)m0 * kD + k0,
            B0 + (size_t)n0 * kD + k0, B1 + (size_t)n0 * kD + k0 };
        #pragma unroll
        for (int tile = 0; tile < 4; tile++) {
            #pragma unroll
            for (int j = 0; j < 2; j++) {
                int lin = tid + j * 256;            // 0..511
                int row = lin >> 2, c16 = lin & 3;  // 16B chunk within 64B row
                const __nv_bfloat16* src = srcs[tile] + (size_t)row * kD + c16 * 8;
                uint32_t dst = smem_u32(base + tile * 8192 +
                                        SMEM_SWIZZLE_64B(row * 64 + c16 * 16));
                CP_ASYNC16(dst, src);
            }
        }
        CP_COMMIT();
    };

    float acc[2][8][4];
    #pragma unroll
    for (int i = 0; i < 2; i++)
        #pragma unroll
        for (int j = 0; j < 8; j++)
            #pragma unroll
            for (int q = 0; q < 4; q++) acc[i][j][q] = 0.0f;

    stage(0, 0);
    stage(1, 1);

    const int nTiles = kD / 32;   // 64
    for (int c = 0; c < nTiles; c++) {
        CP_WAIT1();
        __syncthreads();
        if (c + 2 < nTiles) stage((c + 2) % 3, c + 2);

        const uint32_t base = smem_u32(sm + (c % 3) * 32768);
        const uint32_t a0b = base, a1b = base + 8192;
        const uint32_t b0b = base + 16384, b1b = base + 24576;

        #pragma unroll
        for (int kk = 0; kk < 2; kk++) {
            uint32_t a0f[2][4], a1f[2][4];
            #pragma unroll
            for (int mt = 0; mt < 2; mt++) {
                int row = wm + mt * 16 + (lane & 15);
                uint32_t off = SMEM_SWIZZLE_64B(row * 64 + kk * 32 + (lane >> 4) * 16);
                LDMATRIX_X4(a0f[mt], a0b + off);
                LDMATRIX_X4(a1f[mt], a1b + off);
            }
            #pragma unroll
            for (int p = 0; p < 4; p++) {
                int nrow = wn + p * 16 + (lane & 15);
                uint32_t boff = SMEM_SWIZZLE_64B(nrow * 64 + kk * 32 + (lane >> 4) * 16);
                uint32_t f0[4], f1[4];
                LDMATRIX_X4(f0, b0b + boff);
                LDMATRIX_X4(f1, b1b + boff);
                // mt-interleaved issue; per-acc term order unchanged
                MMA16816(acc[0][2 * p],     a0f[0], f0[0], f0[2]);
                MMA16816(acc[1][2 * p],     a0f[1], f0[0], f0[2]);
                MMA16816(acc[0][2 * p + 1], a0f[0], f0[1], f0[3]);
                MMA16816(acc[1][2 * p + 1], a0f[1], f0[1], f0[3]);
                MMA16816(acc[0][2 * p],     a0f[0], f1[0], f1[2]);
                MMA16816(acc[1][2 * p],     a0f[1], f1[0], f1[2]);
                MMA16816(acc[0][2 * p + 1], a0f[0], f1[1], f1[3]);
                MMA16816(acc[1][2 * p + 1], a0f[1], f1[1], f1[3]);
                MMA16816(acc[0][2 * p],     a1f[0], f0[0], f0[2]);
                MMA16816(acc[1][2 * p],     a1f[1], f0[0], f0[2]);
                MMA16816(acc[0][2 * p + 1], a1f[0], f0[1], f0[3]);
                MMA16816(acc[1][2 * p + 1], a1f[1], f0[1], f0[3]);
            }
        }
    }

    #pragma unroll
    for (int mt = 0; mt < 2; mt++) {
        #pragma unroll
        for (int nt = 0; nt < 8; nt++) {
            int r = m0 + wm + mt * 16 + (lane >> 2);
            int col = n0 + wn + nt * 8 + (lane & 3) * 2;
            float2 v0 = make_float2(acc[mt][nt][0], acc[mt][nt][1]);
            float2 v1 = make_float2(acc[mt][nt][2], acc[mt][nt][3]);
            *reinterpret_cast<float2*>(C + (size_t)r * kD + col) = v0;
            *reinterpret_cast<float2*>(C + (size_t)(r + 8) * kD + col) = v1;
        }
    }
}

// ===========================================================================
// Persistent tensor-core recurrence with GROUP-SCOPED dataflow barrier:
// 8 epoch counters (one per 16-CTA column group). Warp wid gates its staging
// on g_counts[wid] only (its producers), via one relaxed poll + one fence per
// step. Producer side: syncthreads then tid0 red.release to own group.
// ===========================================================================
__global__ __launch_bounds__(256, 1) void rnn_scan_mma_kernel(
    const __nv_bfloat16* __restrict__ WhT0,
    const __nv_bfloat16* __restrict__ WhT1,
    float* __restrict__ hfinal_out)
{
    // dyn smem: [0,64K) h-hi chunks [32][16][64]; [64K,128K) h-lo; [128K,+8K) partials
    extern __shared__ char dsm_raw[];
    const uint32_t raw = smem_u32(dsm_raw);
    const uint32_t base = (raw + 1023u) & ~1023u;
    char* dsm = dsm_raw + (base - raw);
    float* part = reinterpret_cast<float*>(dsm + 131072);

    const int tid = threadIdx.x;
    const int wid = tid >> 5;
    const int lane = tid & 31;
    const int n0 = blockIdx.x * 16;

    unsigned* myCnt  = &g_counts[(blockIdx.x >> 4) * 32];  // arrival target
    unsigned* srcCnt = &g_counts[wid * 32];                // staging gate

    // ---- init: stage Wh^T slice [n0:n0+16][0:2048] hi/lo, extract B frags ----
    {
        const __nv_bfloat16* s0 = WhT0 + (size_t)n0 * kD;
        const __nv_bfloat16* s1 = WhT1 + (size_t)n0 * kD;
        for (int i = tid; i < 4096; i += 256) {
            int row = i >> 8, u = i & 255, ch = u >> 3, c8 = u & 7;
            size_t so = (size_t)row * kD + ch * 64 + c8 * 8;
            uint32_t doff = ch * 2048 + SMEM_SWIZZLE_128B(row * 128 + c8 * 16);
            CP_ASYNC16(base + doff, s0 + so);
            CP_ASYNC16(base + 65536 + doff, s1 + so);
        }
        CP_COMMIT();
        CP_WAIT0();
        __syncthreads();
    }

    uint32_t bh[16][4], bl[16][4];       // 128 regs of resident Wh fragments
    #pragma unroll
    for (int s = 0; s < 16; s++) {
        const int ch = wid * 4 + (s >> 2), kk = s & 3;
        const uint32_t off = ch * 2048 +
            SMEM_SWIZZLE_128B((lane & 15) * 128 + kk * 32 + (lane >> 4) * 16);
        LDMATRIX_X4(bh[s], base + off);
        LDMATRIX_X4(bl[s], base + 65536 + off);
    }
    __syncthreads();   // Wh smem region now reused for h staging

    const int r0 = lane >> 2;
    const int cb = (lane & 3) * 2;
    const int rrow = tid >> 4;            // reduce-phase mapping
    const int rcol = tid & 15;

    // lane-fixed staging geometry (each warp stages only its own 4 chunks)
    const int ld_row_a = lane >> 2;            // rows 0..7
    const int ld_row_b = 8 + (lane >> 2);      // rows 8..15
    const int ld_c8a = (lane & 3) * 2;         // c8 0,2,4,6
    const int ld_c8b = ld_c8a + 1;

    for (int t = 0; t < kT; t++) {
        // per-warp gate: this warp's producers (CTAs wid*16..wid*16+15) have
        // finished step t-1 when g_counts[wid] >= 16*t
        if (t > 0) {
            if (lane == 0) {
                const unsigned target = 16u * (unsigned)t;
                unsigned v;
                do {
                    asm volatile("ld.relaxed.gpu.global.u32 %0, [%1];"
                                 : "=r"(v) : "l"(srcCnt));
                } while (v < target);
            }
            __syncwarp();
            asm volatile("fence.acq_rel.gpu;" ::: "memory");
        }

        const __nv_bfloat16* h0p = g_Hs0 + (size_t)t * kBD;
        const __nv_bfloat16* h1p = g_Hs1 + (size_t)t * kBD;

        // issue 4 pipelined chunk-pair groups (hi+lo), 8 cp.async/lane each
        #pragma unroll
        for (int g = 0; g < 4; g++) {
            const int ch = wid * 4 + g;
            const int rows[2] = {ld_row_a, ld_row_b};
            const int cs[2] = {ld_c8a, ld_c8b};
            #pragma unroll
            for (int ri = 0; ri < 2; ri++) {
                #pragma unroll
                for (int ci = 0; ci < 2; ci++) {
                    const int row = rows[ri], c8 = cs[ci];
                    size_t so = (size_t)row * kD + ch * 64 + c8 * 8;
                    uint32_t doff = ch * 2048 + SMEM_SWIZZLE_128B(row * 128 + c8 * 16);
                    CP_ASYNC16(base + doff, h0p + so);
                    CP_ASYNC16(base + 65536 + doff, h1p + so);
                }
            }
            CP_COMMIT();
        }

        // prefetch Xp bias for this thread's reduce element
        const float xp = __ldg(g_Xp + (size_t)t * kBD + (size_t)rrow * kD + n0 + rcol);

        float acc[2][4];
        #pragma unroll
        for (int p = 0; p < 2; p++)
            #pragma unroll
            for (int q = 0; q < 4; q++) acc[p][q] = 0.0f;

        // consume chunk g as soon as its group lands; later groups keep loading
        #define SCAN_GROUP(gc)                                                   \
        {                                                                        \
            asm volatile("cp.async.wait_group %0;" :: "n"(3 - (gc)) : "memory"); \
            __syncwarp();                                                        \
            const int ch = wid * 4 + (gc);                                       \
            _Pragma("unroll")                                                    \
            for (int kk = 0; kk < 4; kk++) {                                     \
                const int s = (gc) * 4 + kk;                                     \
                const uint32_t off = ch * 2048 +                                 \
                    SMEM_SWIZZLE_128B((lane & 15) * 128 + kk * 32 +              \
                                      (lane >> 4) * 16);                         \
                uint32_t a0[4], a1[4];                                           \
                LDMATRIX_X4(a0, base + off);                                     \
                LDMATRIX_X4(a1, base + 65536 + off);                             \
                MMA16816(acc[0], a0, bh[s][0], bh[s][2]);                        \
                MMA16816(acc[1], a0, bh[s][1], bh[s][3]);                        \
                MMA16816(acc[0], a0, bl[s][0], bl[s][2]);                        \
                MMA16816(acc[1], a0, bl[s][1], bl[s][3]);                        \
                MMA16816(acc[0], a1, bh[s][0], bh[s][2]);                        \
                MMA16816(acc[1], a1, bh[s][1], bh[s][3]);                        \
            }                                                                    \
        }
        SCAN_GROUP(0)
        SCAN_GROUP(1)
        SCAN_GROUP(2)
        SCAN_GROUP(3)
        #undef SCAN_GROUP

        // per-warp partials -> smem
        #pragma unroll
        for (int p = 0; p < 2; p++) {
            *reinterpret_cast<float2*>(&part[wid * 256 + r0 * 16 + p * 8 + cb]) =
                make_float2(acc[p][0], acc[p][1]);
            *reinterpret_cast<float2*>(&part[wid * 256 + (r0 + 8) * 16 + p * 8 + cb]) =
                make_float2(acc[p][2], acc[p][3]);
        }
        __syncthreads();

        // reduce 8 warps + Xp, tanh, split, store
        {
            float s = xp;
            #pragma unroll
            for (int w = 0; w < 8; w++) s += part[w * 256 + tid];
            float h = tanhf(s);
            __nv_bfloat16 hb = __float2bfloat16_rn(h);
            size_t go = (size_t)(t + 1) * kBD + (size_t)rrow * kD + n0 + rcol;
            g_Hs0[go] = hb;
            g_Hs1[go] = __float2bfloat16_rn(h - __bfloat162float(hb));
            if (t == kT - 1)
                hfinal_out[(size_t)rrow * kD + n0 + rcol] = h;
        }

        // publish: all h stores done (syncthreads also protects the partials
        // region from next step's writes), then release-arrive on own group
        __syncthreads();
        if (t + 1 < kT && tid == 0) {
            asm volatile("red.release.gpu.global.add.u32 [%0], 1;"
                         :: "l"(myCnt) : "memory");
        }
    }
}

// ===========================================================================
// Launch
// ===========================================================================
extern "C" void kernel_launch(void* const* d_in, const int* in_sizes, int n_in,
                              void* d_out, int out_size)
{
    const float* h0 = (const float*)d_in[0];
    const float* x  = (const float*)d_in[1];
    const float* Wx = (const float*)d_in[2];
    const float* Wh = (const float*)d_in[3];
    const float* Wo = (const float*)d_in[4];

    float* out  = (float*)d_out;
    float* hfin = out;                 // [B, D]
    float* ys   = out + kBD;           // [T, B, D]

    float* Xp;
    __nv_bfloat16 *Hs0, *Hs1, *Xs0, *Xs1, *WxT0, *WxT1, *WoT0, *WoT1, *WhT0, *WhT1;
    cudaGetSymbolAddress((void**)&Xp,   g_Xp);
    cudaGetSymbolAddress((void**)&Hs0,  g_Hs0);
    cudaGetSymbolAddress((void**)&Hs1,  g_Hs1);
    cudaGetSymbolAddress((void**)&Xs0,  g_Xs0);
    cudaGetSymbolAddress((void**)&Xs1,  g_Xs1);
    cudaGetSymbolAddress((void**)&WxT0, g_WxT0);
    cudaGetSymbolAddress((void**)&WxT1, g_WxT1);
    cudaGetSymbolAddress((void**)&WoT0, g_WoT0);
    cudaGetSymbolAddress((void**)&WoT1, g_WoT1);
    cudaGetSymbolAddress((void**)&WhT0, g_WhT0);
    cudaGetSymbolAddress((void**)&WhT1, g_WhT1);

    const int gemm_smem = 3 * 32768;                 // 96 KB
    const int scan_smem = 131072 + 8192 + 1024;      // 140 KB
    cudaFuncSetAttribute(gemm_bf16_kernel,
                         cudaFuncAttributeMaxDynamicSharedMemorySize, gemm_smem);
    cudaFuncSetAttribute(rnn_scan_mma_kernel,
                         cudaFuncAttributeMaxDynamicSharedMemorySize, scan_smem);

    // 1 launch: transpose+split all three weights, reset group counters
    dim3 prep_grid(kD / 32, kD / 32, 3), prep_blk(32, 32);
    prep_wT3_kernel<<<prep_grid, prep_blk>>>(Wx, Wh, Wo,
                                             WxT0, WxT1, WhT0, WhT1, WoT0, WoT1);

    // 1 launch: split x AND h0
    const int n4x = kM * kD / 4;
    const int n4h = kBD / 4;
    const int nsplit = n4x + n4h;
    split2_kernel<<<(nsplit + 255) / 256, 256>>>(x, Xs0, Xs1, n4x,
                                                 h0, Hs0, Hs1, n4h);

    dim3 gemm_grid(kD / 128, kM / 128);   // (16, 64)

    // Xp = X @ Wx  (HMMA bf16x3, v6)
    gemm_bf16_kernel<<<gemm_grid, 256, gemm_smem>>>(Xs0, Xs1, WxT0, WxT1, Xp);

    // sequential scan: tensor-core recurrence, group-scoped dataflow barrier
    rnn_scan_mma_kernel<<<128, 256, scan_smem>>>(WhT0, WhT1, hfin);

    // ys = H @ Wo  (HMMA bf16x3; A = Hs slots 1..T)
    gemm_bf16_kernel<<<gemm_grid, 256, gemm_smem>>>(Hs0 + kBD, Hs1 + kBD,
                                                    WoT0, WoT1, ys);
}

// round 15
// speedup vs baseline: 1.2552x; 1.2552x over previous
#include <cuda_runtime.h>
#include <cuda_bf16.h>
#include <math.h>
#include <stdint.h>

static constexpr int kT = 512;
static constexpr int kB = 16;
static constexpr int kD = 2048;
static constexpr int kBD = kB * kD;          // 32768
static constexpr int kM = kT * kB;           // 8192 rows in big GEMMs

// Scratch (device globals; no allocation allowed)
__device__ float g_Xp[kT * kBD];                 // X @ Wx   [T*B, D]
__device__ __nv_bfloat16 g_Hs0[(kT + 1) * kBD]; // h bf16 hi; slot t = h_{t-1}
__device__ __nv_bfloat16 g_Hs1[(kT + 1) * kBD]; // h bf16 lo
__device__ __nv_bfloat16 g_Xs0[kM * kD];         // x bf16 hi
__device__ __nv_bfloat16 g_Xs1[kM * kD];         // x bf16 lo
__device__ __nv_bfloat16 g_WxT0[kD * kD];        // W^T splits, [N][K]
__device__ __nv_bfloat16 g_WxT1[kD * kD];
__device__ __nv_bfloat16 g_WoT0[kD * kD];
__device__ __nv_bfloat16 g_WoT1[kD * kD];
__device__ __nv_bfloat16 g_WhT0[kD * kD];
__device__ __nv_bfloat16 g_WhT1[kD * kD];
__device__ unsigned g_count = 0;                 // epoch barrier counter

// ===========================================================================
// PTX helpers — base sm_103 ISA only (no 'a'-gated features)
// ===========================================================================
__device__ __forceinline__ uint32_t smem_u32(const void* p) {
    uint32_t a;
    asm("{ .reg .u64 t; cvta.to.shared.u64 t, %1; cvt.u32.u64 %0, t; }"
        : "=r"(a) : "l"(p));
    return a;
}
#define CP_ASYNC16(dst, src) \
    asm volatile("cp.async.cg.shared.global [%0], [%1], 16;" \
                 :: "r"(dst), "l"(src) : "memory")
#define CP_COMMIT() asm volatile("cp.async.commit_group;" ::: "memory")
#define CP_WAIT1()  asm volatile("cp.async.wait_group 1;" ::: "memory")
#define CP_WAIT0()  asm volatile("cp.async.wait_group 0;" ::: "memory")

#define LDMATRIX_X4(r, addr) \
    asm volatile("ldmatrix.sync.aligned.m8n8.x4.shared.b16 {%0,%1,%2,%3}, [%4];" \
        : "=r"((r)[0]), "=r"((r)[1]), "=r"((r)[2]), "=r"((r)[3]) : "r"(addr))

#define MMA16816(d, a, b0, b1) \
    asm volatile("mma.sync.aligned.m16n8k16.row.col.f32.bf16.bf16.f32 " \
        "{%0,%1,%2,%3}, {%4,%5,%6,%7}, {%8,%9}, {%0,%1,%2,%3};" \
        : "+f"((d)[0]), "+f"((d)[1]), "+f"((d)[2]), "+f"((d)[3]) \
        : "r"((a)[0]), "r"((a)[1]), "r"((a)[2]), "r"((a)[3]), "r"(b0), "r"(b1))

#define SMEM_SWIZZLE_128B(x) ((x) ^ (((x) >> 3) & 0x70))
#define SMEM_SWIZZLE_64B(x)  ((x) ^ (((x) >> 3) & 0x30))

__device__ __forceinline__ unsigned pack_bf2(__nv_bfloat16 a, __nv_bfloat16 b) {
    __nv_bfloat162 h = __halves2bfloat162(a, b);
    return *reinterpret_cast<unsigned*>(&h);
}

// ===========================================================================
// Fused prep: transpose+split ALL THREE weights in one launch (grid.z picks
// the matrix); also zeroes the epoch counter (stream-ordered before scan).
// ===========================================================================
__global__ void prep_wT3_kernel(const float* __restrict__ Wx,
                                const float* __restrict__ Wh,
                                const float* __restrict__ Wo,
                                __nv_bfloat16* __restrict__ WxT0,
                                __nv_bfloat16* __restrict__ WxT1,
                                __nv_bfloat16* __restrict__ WhT0,
                                __nv_bfloat16* __restrict__ WhT1,
                                __nv_bfloat16* __restrict__ WoT0,
                                __nv_bfloat16* __restrict__ WoT1)
{
    const float* W;
    __nv_bfloat16 *T0, *T1;
    if (blockIdx.z == 0)      { W = Wx; T0 = WxT0; T1 = WxT1; }
    else if (blockIdx.z == 1) { W = Wh; T0 = WhT0; T1 = WhT1; }
    else                      { W = Wo; T0 = WoT0; T1 = WoT1; }

    __shared__ float tile[32][33];
    const int n0 = blockIdx.x * 32, k0 = blockIdx.y * 32;
    const int tx = threadIdx.x, ty = threadIdx.y;
    tile[ty][tx] = W[(size_t)(k0 + ty) * kD + n0 + tx];
    __syncthreads();
    float v = tile[tx][ty];                       // = W[k0+tx][n0+ty]
    __nv_bfloat16 b0 = __float2bfloat16_rn(v);
    float r = v - __bfloat162float(b0);
    __nv_bfloat16 b1 = __float2bfloat16_rn(r);
    size_t o = (size_t)(n0 + ty) * kD + k0 + tx;  // T[n][k]
    T0[o] = b0;
    T1[o] = b1;

    if (blockIdx.x == 0 && blockIdx.y == 0 && blockIdx.z == 0 &&
        tx == 0 && ty == 0)
        g_count = 0;                              // fold in barrier reset
}

// Fused fp32 -> bf16 hi/lo split for x AND h0 in one launch.
__global__ void split2_kernel(const float* __restrict__ x,
                              __nv_bfloat16* __restrict__ xo0,
                              __nv_bfloat16* __restrict__ xo1, int n4x,
                              const float* __restrict__ h,
                              __nv_bfloat16* __restrict__ ho0,
                              __nv_bfloat16* __restrict__ ho1, int n4h)
{
    int i = blockIdx.x * blockDim.x + threadIdx.x;
    const float* in;
    __nv_bfloat16 *o0, *o1;
    int idx;
    if (i < n4x) { in = x; o0 = xo0; o1 = xo1; idx = i; }
    else {
        idx = i - n4x;
        if (idx >= n4h) return;
        in = h; o0 = ho0; o1 = ho1;
    }
    float4 v = __ldg(reinterpret_cast<const float4*>(in) + idx);
    __nv_bfloat16 hx = __float2bfloat16_rn(v.x);
    __nv_bfloat16 hy = __float2bfloat16_rn(v.y);
    __nv_bfloat16 hz = __float2bfloat16_rn(v.z);
    __nv_bfloat16 hw = __float2bfloat16_rn(v.w);
    __nv_bfloat16 lx = __float2bfloat16_rn(v.x - __bfloat162float(hx));
    __nv_bfloat16 ly = __float2bfloat16_rn(v.y - __bfloat162float(hy));
    __nv_bfloat16 lz = __float2bfloat16_rn(v.z - __bfloat162float(hz));
    __nv_bfloat16 lw = __float2bfloat16_rn(v.w - __bfloat162float(hw));
    uint2 p0 = make_uint2(pack_bf2(hx, hy), pack_bf2(hz, hw));
    uint2 p1 = make_uint2(pack_bf2(lx, ly), pack_bf2(lz, lw));
    reinterpret_cast<uint2*>(o0)[idx] = p0;
    reinterpret_cast<uint2*>(o1)[idx] = p1;
}

// ===========================================================================
// HMMA bf16x3 GEMM v6 (unchanged): 128x128 tile, BK=32, 3-stage cp.async,
// 256 thr / 8 warps, mt-interleaved MMA issue. Near the mma.sync pipe ceiling.
// ===========================================================================
__global__ __launch_bounds__(256, 2) void gemm_bf16_kernel(
    const __nv_bfloat16* __restrict__ A0, const __nv_bfloat16* __restrict__ A1,
    const __nv_bfloat16* __restrict__ B0, const __nv_bfloat16* __restrict__ B1,
    float* __restrict__ C)
{
    extern __shared__ char sm[];   // [3 stages][4 tiles][8192B]; tile=[128][32] bf16

    const int tid = threadIdx.x;
    const int wid = tid >> 5;
    const int lane = tid & 31;
    const int m0 = blockIdx.y * 128, n0 = blockIdx.x * 128;
    const int wm = (wid & 3) * 32;
    const int wn = (wid >> 2) * 64;

    auto stage = [&](int buf, int c) {
        const int k0 = c * 32;
        char* base = sm + buf * 32768;
        const __nv_bfloat16* srcs[4] = {
            A0 + (size_t)m0 * kD + k0, A1 + (size_t)m0 * kD + k0,
            B0 + (size_t)n0 * kD + k0, B1 + (size_t)n0 * kD + k0 };
        #pragma unroll
        for (int tile = 0; tile < 4; tile++) {
            #pragma unroll
            for (int j = 0; j < 2; j++) {
                int lin = tid + j * 256;            // 0..511
                int row = lin >> 2, c16 = lin & 3;  // 16B chunk within 64B row
                const __nv_bfloat16* src = srcs[tile] + (size_t)row * kD + c16 * 8;
                uint32_t dst = smem_u32(base + tile * 8192 +
                                        SMEM_SWIZZLE_64B(row * 64 + c16 * 16));
                CP_ASYNC16(dst, src);
            }
        }
        CP_COMMIT();
    };

    float acc[2][8][4];
    #pragma unroll
    for (int i = 0; i < 2; i++)
        #pragma unroll
        for (int j = 0; j < 8; j++)
            #pragma unroll
            for (int q = 0; q < 4; q++) acc[i][j][q] = 0.0f;

    stage(0, 0);
    stage(1, 1);

    const int nTiles = kD / 32;   // 64
    for (int c = 0; c < nTiles; c++) {
        CP_WAIT1();
        __syncthreads();
        if (c + 2 < nTiles) stage((c + 2) % 3, c + 2);

        const uint32_t base = smem_u32(sm + (c % 3) * 32768);
        const uint32_t a0b = base, a1b = base + 8192;
        const uint32_t b0b = base + 16384, b1b = base + 24576;

        #pragma unroll
        for (int kk = 0; kk < 2; kk++) {
            uint32_t a0f[2][4], a1f[2][4];
            #pragma unroll
            for (int mt = 0; mt < 2; mt++) {
                int row = wm + mt * 16 + (lane & 15);
                uint32_t off = SMEM_SWIZZLE_64B(row * 64 + kk * 32 + (lane >> 4) * 16);
                LDMATRIX_X4(a0f[mt], a0b + off);
                LDMATRIX_X4(a1f[mt], a1b + off);
            }
            #pragma unroll
            for (int p = 0; p < 4; p++) {
                int nrow = wn + p * 16 + (lane & 15);
                uint32_t boff = SMEM_SWIZZLE_64B(nrow * 64 + kk * 32 + (lane >> 4) * 16);
                uint32_t f0[4], f1[4];
                LDMATRIX_X4(f0, b0b + boff);
                LDMATRIX_X4(f1, b1b + boff);
                // mt-interleaved issue; per-acc term order unchanged
                MMA16816(acc[0][2 * p],     a0f[0], f0[0], f0[2]);
                MMA16816(acc[1][2 * p],     a0f[1], f0[0], f0[2]);
                MMA16816(acc[0][2 * p + 1], a0f[0], f0[1], f0[3]);
                MMA16816(acc[1][2 * p + 1], a0f[1], f0[1], f0[3]);
                MMA16816(acc[0][2 * p],     a0f[0], f1[0], f1[2]);
                MMA16816(acc[1][2 * p],     a0f[1], f1[0], f1[2]);
                MMA16816(acc[0][2 * p + 1], a0f[0], f1[1], f1[3]);
                MMA16816(acc[1][2 * p + 1], a0f[1], f1[1], f1[3]);
                MMA16816(acc[0][2 * p],     a1f[0], f0[0], f0[2]);
                MMA16816(acc[1][2 * p],     a1f[1], f0[0], f0[2]);
                MMA16816(acc[0][2 * p + 1], a1f[0], f0[1], f0[3]);
                MMA16816(acc[1][2 * p + 1], a1f[1], f0[1], f0[3]);
            }
        }
    }

    #pragma unroll
    for (int mt = 0; mt < 2; mt++) {
        #pragma unroll
        for (int nt = 0; nt < 8; nt++) {
            int r = m0 + wm + mt * 16 + (lane >> 2);
            int col = n0 + wn + nt * 8 + (lane & 3) * 2;
            float2 v0 = make_float2(acc[mt][nt][0], acc[mt][nt][1]);
            float2 v1 = make_float2(acc[mt][nt][2], acc[mt][nt][3]);
            *reinterpret_cast<float2*>(C + (size_t)r * kD + col) = v0;
            *reinterpret_cast<float2*>(C + (size_t)(r + 8) * kD + col) = v1;
        }
    }
}

// ===========================================================================
// Persistent tensor-core recurrence (R13 design — proven optimum). Epoch-REDG
// global barrier; single tid0 poller. Only change vs R13: Xp prefetch hoisted
// above cp.async staging so its L2 latency overlaps the staging issue.
// ===========================================================================
__global__ __launch_bounds__(256, 1) void rnn_scan_mma_kernel(
    const __nv_bfloat16* __restrict__ WhT0,
    const __nv_bfloat16* __restrict__ WhT1,
    float* __restrict__ hfinal_out)
{
    // dyn smem: [0,64K) h-hi chunks [32][16][64]; [64K,128K) h-lo; [128K,+8K) partials
    extern __shared__ char dsm_raw[];
    const uint32_t raw = smem_u32(dsm_raw);
    const uint32_t base = (raw + 1023u) & ~1023u;
    char* dsm = dsm_raw + (base - raw);
    float* part = reinterpret_cast<float*>(dsm + 131072);

    const int tid = threadIdx.x;
    const int wid = tid >> 5;
    const int lane = tid & 31;
    const int n0 = blockIdx.x * 16;

    unsigned* cnt = &g_count;

    // ---- init: stage Wh^T slice [n0:n0+16][0:2048] hi/lo, extract B frags ----
    {
        const __nv_bfloat16* s0 = WhT0 + (size_t)n0 * kD;
        const __nv_bfloat16* s1 = WhT1 + (size_t)n0 * kD;
        for (int i = tid; i < 4096; i += 256) {
            int row = i >> 8, u = i & 255, ch = u >> 3, c8 = u & 7;
            size_t so = (size_t)row * kD + ch * 64 + c8 * 8;
            uint32_t doff = ch * 2048 + SMEM_SWIZZLE_128B(row * 128 + c8 * 16);
            CP_ASYNC16(base + doff, s0 + so);
            CP_ASYNC16(base + 65536 + doff, s1 + so);
        }
        CP_COMMIT();
        CP_WAIT0();
        __syncthreads();
    }

    uint32_t bh[16][4], bl[16][4];       // 128 regs of resident Wh fragments
    #pragma unroll
    for (int s = 0; s < 16; s++) {
        const int ch = wid * 4 + (s >> 2), kk = s & 3;
        const uint32_t off = ch * 2048 +
            SMEM_SWIZZLE_128B((lane & 15) * 128 + kk * 32 + (lane >> 4) * 16);
        LDMATRIX_X4(bh[s], base + off);
        LDMATRIX_X4(bl[s], base + 65536 + off);
    }
    __syncthreads();   // Wh smem region now reused for h staging

    const int r0 = lane >> 2;
    const int cb = (lane & 3) * 2;
    const int rrow = tid >> 4;            // reduce-phase mapping
    const int rcol = tid & 15;

    // lane-fixed staging geometry (each warp stages only its own 4 chunks)
    const int ld_row_a = lane >> 2;            // rows 0..7
    const int ld_row_b = 8 + (lane >> 2);      // rows 8..15
    const int ld_c8a = (lane & 3) * 2;         // c8 0,2,4,6
    const int ld_c8b = ld_c8a + 1;

    for (int t = 0; t < kT; t++) {
        const __nv_bfloat16* h0p = g_Hs0 + (size_t)t * kBD;
        const __nv_bfloat16* h1p = g_Hs1 + (size_t)t * kBD;

        // prefetch Xp bias FIRST: its L2 latency overlaps the staging issue
        const float xp = __ldg(g_Xp + (size_t)t * kBD + (size_t)rrow * kD + n0 + rcol);

        // issue 4 pipelined chunk-pair groups (hi+lo), 8 cp.async/lane each
        #pragma unroll
        for (int g = 0; g < 4; g++) {
            const int ch = wid * 4 + g;
            const int rows[2] = {ld_row_a, ld_row_b};
            const int cs[2] = {ld_c8a, ld_c8b};
            #pragma unroll
            for (int ri = 0; ri < 2; ri++) {
                #pragma unroll
                for (int ci = 0; ci < 2; ci++) {
                    const int row = rows[ri], c8 = cs[ci];
                    size_t so = (size_t)row * kD + ch * 64 + c8 * 8;
                    uint32_t doff = ch * 2048 + SMEM_SWIZZLE_128B(row * 128 + c8 * 16);
                    CP_ASYNC16(base + doff, h0p + so);
                    CP_ASYNC16(base + 65536 + doff, h1p + so);
                }
            }
            CP_COMMIT();
        }

        float acc[2][4];
        #pragma unroll
        for (int p = 0; p < 2; p++)
            #pragma unroll
            for (int q = 0; q < 4; q++) acc[p][q] = 0.0f;

        // consume chunk g as soon as its group lands; later groups keep loading
        #define SCAN_GROUP(gc)                                                   \
        {                                                                        \
            asm volatile("cp.async.wait_group %0;" :: "n"(3 - (gc)) : "memory"); \
            __syncwarp();                                                        \
            const int ch = wid * 4 + (gc);                                       \
            _Pragma("unroll")                                                    \
            for (int kk = 0; kk < 4; kk++) {                                     \
                const int s = (gc) * 4 + kk;                                     \
                const uint32_t off = ch * 2048 +                                 \
                    SMEM_SWIZZLE_128B((lane & 15) * 128 + kk * 32 +              \
                                      (lane >> 4) * 16);                         \
                uint32_t a0[4], a1[4];                                           \
                LDMATRIX_X4(a0, base + off);                                     \
                LDMATRIX_X4(a1, base + 65536 + off);                             \
                MMA16816(acc[0], a0, bh[s][0], bh[s][2]);                        \
                MMA16816(acc[1], a0, bh[s][1], bh[s][3]);                        \
                MMA16816(acc[0], a0, bl[s][0], bl[s][2]);                        \
                MMA16816(acc[1], a0, bl[s][1], bl[s][3]);                        \
                MMA16816(acc[0], a1, bh[s][0], bh[s][2]);                        \
                MMA16816(acc[1], a1, bh[s][1], bh[s][3]);                        \
            }                                                                    \
        }
        SCAN_GROUP(0)
        SCAN_GROUP(1)
        SCAN_GROUP(2)
        SCAN_GROUP(3)
        #undef SCAN_GROUP

        // per-warp partials -> smem
        #pragma unroll
        for (int p = 0; p < 2; p++) {
            *reinterpret_cast<float2*>(&part[wid * 256 + r0 * 16 + p * 8 + cb]) =
                make_float2(acc[p][0], acc[p][1]);
            *reinterpret_cast<float2*>(&part[wid * 256 + (r0 + 8) * 16 + p * 8 + cb]) =
                make_float2(acc[p][2], acc[p][3]);
        }
        __syncthreads();

        // reduce 8 warps + Xp, tanh, split, store
        {
            float s = xp;
            #pragma unroll
            for (int w = 0; w < 8; w++) s += part[w * 256 + tid];
            float h = tanhf(s);
            __nv_bfloat16 hb = __float2bfloat16_rn(h);
            size_t go = (size_t)(t + 1) * kBD + (size_t)rrow * kD + n0 + rcol;
            g_Hs0[go] = hb;
            g_Hs1[go] = __float2bfloat16_rn(h - __bfloat162float(hb));
            if (t == kT - 1)
                hfinal_out[(size_t)rrow * kD + n0 + rcol] = h;
        }

        // epoch barrier: REDG arrival, poll monotonic counter for 128*(t+1)
        if (t + 1 < kT) {
            __syncthreads();
            if (tid == 0) {
                asm volatile("fence.acq_rel.gpu;" ::: "memory");
                asm volatile("red.relaxed.gpu.global.add.u32 [%0], 1;"
                             :: "l"(cnt) : "memory");
                const unsigned target = 128u * (unsigned)(t + 1);
                unsigned v;
                do {
                    asm volatile("ld.relaxed.gpu.global.u32 %0, [%1];"
                                 : "=r"(v) : "l"(cnt));
                } while (v < target);
                asm volatile("fence.acq_rel.gpu;" ::: "memory");
            }
            __syncthreads();
        }
    }
}

// ===========================================================================
// Launch
// ===========================================================================
extern "C" void kernel_launch(void* const* d_in, const int* in_sizes, int n_in,
                              void* d_out, int out_size)
{
    const float* h0 = (const float*)d_in[0];
    const float* x  = (const float*)d_in[1];
    const float* Wx = (const float*)d_in[2];
    const float* Wh = (const float*)d_in[3];
    const float* Wo = (const float*)d_in[4];

    float* out  = (float*)d_out;
    float* hfin = out;                 // [B, D]
    float* ys   = out + kBD;           // [T, B, D]

    float* Xp;
    __nv_bfloat16 *Hs0, *Hs1, *Xs0, *Xs1, *WxT0, *WxT1, *WoT0, *WoT1, *WhT0, *WhT1;
    cudaGetSymbolAddress((void**)&Xp,   g_Xp);
    cudaGetSymbolAddress((void**)&Hs0,  g_Hs0);
    cudaGetSymbolAddress((void**)&Hs1,  g_Hs1);
    cudaGetSymbolAddress((void**)&Xs0,  g_Xs0);
    cudaGetSymbolAddress((void**)&Xs1,  g_Xs1);
    cudaGetSymbolAddress((void**)&WxT0, g_WxT0);
    cudaGetSymbolAddress((void**)&WxT1, g_WxT1);
    cudaGetSymbolAddress((void**)&WoT0, g_WoT0);
    cudaGetSymbolAddress((void**)&WoT1, g_WoT1);
    cudaGetSymbolAddress((void**)&WhT0, g_WhT0);
    cudaGetSymbolAddress((void**)&WhT1, g_WhT1);

    const int gemm_smem = 3 * 32768;                 // 96 KB
    const int scan_smem = 131072 + 8192 + 1024;      // 140 KB
    cudaFuncSetAttribute(gemm_bf16_kernel,
                         cudaFuncAttributeMaxDynamicSharedMemorySize, gemm_smem);
    cudaFuncSetAttribute(rnn_scan_mma_kernel,
                         cudaFuncAttributeMaxDynamicSharedMemorySize, scan_smem);

    // 1 launch: transpose+split all three weights, reset barrier counter
    dim3 prep_grid(kD / 32, kD / 32, 3), prep_blk(32, 32);
    prep_wT3_kernel<<<prep_grid, prep_blk>>>(Wx, Wh, Wo,
                                             WxT0, WxT1, WhT0, WhT1, WoT0, WoT1);

    // 1 launch: split x AND h0
    const int n4x = kM * kD / 4;
    const int n4h = kBD / 4;
    const int nsplit = n4x + n4h;
    split2_kernel<<<(nsplit + 255) / 256, 256>>>(x, Xs0, Xs1, n4x,
                                                 h0, Hs0, Hs1, n4h);

    dim3 gemm_grid(kD / 128, kM / 128);   // (16, 64)

    // Xp = X @ Wx  (HMMA bf16x3, v6)
    gemm_bf16_kernel<<<gemm_grid, 256, gemm_smem>>>(Xs0, Xs1, WxT0, WxT1, Xp);

    // sequential scan: tensor-core recurrence, epoch-REDG barrier
    rnn_scan_mma_kernel<<<128, 256, scan_smem>>>(WhT0, WhT1, hfin);

    // ys = H @ Wo  (HMMA bf16x3; A = Hs slots 1..T)
    gemm_bf16_kernel<<<gemm_grid, 256, gemm_smem>>>(Hs0 + kBD, Hs1 + kBD,
                                                    WoT0, WoT1, ys);
}

// round 16
// speedup vs baseline: 1.2897x; 1.0275x over previous
#include <cuda_runtime.h>
#include <cuda_bf16.h>
#include <math.h>
#include <stdint.h>

static constexpr int kT = 512;
static constexpr int kB = 16;
static constexpr int kD = 2048;
static constexpr int kBD = kB * kD;          // 32768
static constexpr int kM = kT * kB;           // 8192 rows in big GEMMs
static constexpr int kYTiles = (kM / 128) * (kD / 128);   // 1024 Y-GEMM tiles

// Scratch (device globals; no allocation allowed)
__device__ float g_Xp[kT * kBD];                 // X @ Wx   [T*B, D]
__device__ __nv_bfloat16 g_Hs0[(kT + 1) * kBD]; // h bf16 hi; slot t = h_{t-1}
__device__ __nv_bfloat16 g_Hs1[(kT + 1) * kBD]; // h bf16 lo
__device__ __nv_bfloat16 g_Xs0[kM * kD];         // x bf16 hi
__device__ __nv_bfloat16 g_Xs1[kM * kD];         // x bf16 lo
__device__ __nv_bfloat16 g_WxT0[kD * kD];        // W^T splits, [N][K]
__device__ __nv_bfloat16 g_WxT1[kD * kD];
__device__ __nv_bfloat16 g_WoT0[kD * kD];
__device__ __nv_bfloat16 g_WoT1[kD * kD];
__device__ __nv_bfloat16 g_WhT0[kD * kD];
__device__ __nv_bfloat16 g_WhT1[kD * kD];
__device__ unsigned g_count = 0;                 // scan epoch counter
__device__ unsigned g_ytile = 0;                 // Y-GEMM tile work queue

// ===========================================================================
// PTX helpers — base sm_103 ISA only (no 'a'-gated features)
// ===========================================================================
__device__ __forceinline__ uint32_t smem_u32(const void* p) {
    uint32_t a;
    asm("{ .reg .u64 t; cvta.to.shared.u64 t, %1; cvt.u32.u64 %0, t; }"
        : "=r"(a) : "l"(p));
    return a;
}
#define CP_ASYNC16(dst, src) \
    asm volatile("cp.async.cg.shared.global [%0], [%1], 16;" \
                 :: "r"(dst), "l"(src) : "memory")
#define CP_COMMIT() asm volatile("cp.async.commit_group;" ::: "memory")
#define CP_WAIT1()  asm volatile("cp.async.wait_group 1;" ::: "memory")
#define CP_WAIT0()  asm volatile("cp.async.wait_group 0;" ::: "memory")

#define LDMATRIX_X4(r, addr) \
    asm volatile("ldmatrix.sync.aligned.m8n8.x4.shared.b16 {%0,%1,%2,%3}, [%4];" \
        : "=r"((r)[0]), "=r"((r)[1]), "=r"((r)[2]), "=r"((r)[3]) : "r"(addr))

#define MMA16816(d, a, b0, b1) \
    asm volatile("mma.sync.aligned.m16n8k16.row.col.f32.bf16.bf16.f32 " \
        "{%0,%1,%2,%3}, {%4,%5,%6,%7}, {%8,%9}, {%0,%1,%2,%3};" \
        : "+f"((d)[0]), "+f"((d)[1]), "+f"((d)[2]), "+f"((d)[3]) \
        : "r"((a)[0]), "r"((a)[1]), "r"((a)[2]), "r"((a)[3]), "r"(b0), "r"(b1))

#define SMEM_SWIZZLE_128B(x) ((x) ^ (((x) >> 3) & 0x70))
#define SMEM_SWIZZLE_64B(x)  ((x) ^ (((x) >> 3) & 0x30))

__device__ __forceinline__ unsigned pack_bf2(__nv_bfloat16 a, __nv_bfloat16 b) {
    __nv_bfloat162 h = __halves2bfloat162(a, b);
    return *reinterpret_cast<unsigned*>(&h);
}

// ===========================================================================
// Fused prep: transpose+split ALL THREE weights; zero epoch + work counters.
// ===========================================================================
__global__ void prep_wT3_kernel(const float* __restrict__ Wx,
                                const float* __restrict__ Wh,
                                const float* __restrict__ Wo,
                                __nv_bfloat16* __restrict__ WxT0,
                                __nv_bfloat16* __restrict__ WxT1,
                                __nv_bfloat16* __restrict__ WhT0,
                                __nv_bfloat16* __restrict__ WhT1,
                                __nv_bfloat16* __restrict__ WoT0,
                                __nv_bfloat16* __restrict__ WoT1)
{
    const float* W;
    __nv_bfloat16 *T0, *T1;
    if (blockIdx.z == 0)      { W = Wx; T0 = WxT0; T1 = WxT1; }
    else if (blockIdx.z == 1) { W = Wh; T0 = WhT0; T1 = WhT1; }
    else                      { W = Wo; T0 = WoT0; T1 = WoT1; }

    __shared__ float tile[32][33];
    const int n0 = blockIdx.x * 32, k0 = blockIdx.y * 32;
    const int tx = threadIdx.x, ty = threadIdx.y;
    tile[ty][tx] = W[(size_t)(k0 + ty) * kD + n0 + tx];
    __syncthreads();
    float v = tile[tx][ty];                       // = W[k0+tx][n0+ty]
    __nv_bfloat16 b0 = __float2bfloat16_rn(v);
    float r = v - __bfloat162float(b0);
    __nv_bfloat16 b1 = __float2bfloat16_rn(r);
    size_t o = (size_t)(n0 + ty) * kD + k0 + tx;  // T[n][k]
    T0[o] = b0;
    T1[o] = b1;

    if (blockIdx.x == 0 && blockIdx.y == 0 && blockIdx.z == 0 &&
        tx == 0 && ty == 0) {
        g_count = 0;
        g_ytile = 0;
    }
}

// Fused fp32 -> bf16 hi/lo split for x AND h0 in one launch.
__global__ void split2_kernel(const float* __restrict__ x,
                              __nv_bfloat16* __restrict__ xo0,
                              __nv_bfloat16* __restrict__ xo1, int n4x,
                              const float* __restrict__ h,
                              __nv_bfloat16* __restrict__ ho0,
                              __nv_bfloat16* __restrict__ ho1, int n4h)
{
    int i = blockIdx.x * blockDim.x + threadIdx.x;
    const float* in;
    __nv_bfloat16 *o0, *o1;
    int idx;
    if (i < n4x) { in = x; o0 = xo0; o1 = xo1; idx = i; }
    else {
        idx = i - n4x;
        if (idx >= n4h) return;
        in = h; o0 = ho0; o1 = ho1;
    }
    float4 v = __ldg(reinterpret_cast<const float4*>(in) + idx);
    __nv_bfloat16 hx = __float2bfloat16_rn(v.x);
    __nv_bfloat16 hy = __float2bfloat16_rn(v.y);
    __nv_bfloat16 hz = __float2bfloat16_rn(v.z);
    __nv_bfloat16 hw = __float2bfloat16_rn(v.w);
    __nv_bfloat16 lx = __float2bfloat16_rn(v.x - __bfloat162float(hx));
    __nv_bfloat16 ly = __float2bfloat16_rn(v.y - __bfloat162float(hy));
    __nv_bfloat16 lz = __float2bfloat16_rn(v.z - __bfloat162float(hz));
    __nv_bfloat16 lw = __float2bfloat16_rn(v.w - __bfloat162float(hw));
    uint2 p0 = make_uint2(pack_bf2(hx, hy), pack_bf2(hz, hw));
    uint2 p1 = make_uint2(pack_bf2(lx, ly), pack_bf2(lz, lw));
    reinterpret_cast<uint2*>(o0)[idx] = p0;
    reinterpret_cast<uint2*>(o1)[idx] = p1;
}

// ===========================================================================
// GEMM v6 tile body (shared by Xp GEMM, scan helpers, and Y tail kernel):
// one 128x128 C tile, BK=32, 3-stage cp.async, 8 warps, mt-interleaved MMA.
// Identical math/order to R12/R13 -> bit-identical results.
// ===========================================================================
__device__ __forceinline__ void gemm_tile_body(
    const __nv_bfloat16* __restrict__ A0, const __nv_bfloat16* __restrict__ A1,
    const __nv_bfloat16* __restrict__ B0, const __nv_bfloat16* __restrict__ B1,
    float* __restrict__ C, int m0, int n0, char* sm,
    int tid, int wid, int lane)
{
    const int wm = (wid & 3) * 32;
    const int wn = (wid >> 2) * 64;

    auto stage = [&](int buf, int c) {
        const int k0 = c * 32;
        char* base = sm + buf * 32768;
        const __nv_bfloat16* srcs[4] = {
            A0 + (size_t)m0 * kD + k0, A1 + (size_t)m0 * kD + k0,
            B0 + (size_t)n0 * kD + k0, B1 + (size_t)n0 * kD + k0 };
        #pragma unroll
        for (int tile = 0; tile < 4; tile++) {
            #pragma unroll
            for (int j = 0; j < 2; j++) {
                int lin = tid + j * 256;            // 0..511
                int row = lin >> 2, c16 = lin & 3;  // 16B chunk within 64B row
                const __nv_bfloat16* src = srcs[tile] + (size_t)row * kD + c16 * 8;
                uint32_t dst = smem_u32(base + tile * 8192 +
                                        SMEM_SWIZZLE_64B(row * 64 + c16 * 16));
                CP_ASYNC16(dst, src);
            }
        }
        CP_COMMIT();
    };

    float acc[2][8][4];
    #pragma unroll
    for (int i = 0; i < 2; i++)
        #pragma unroll
        for (int j = 0; j < 8; j++)
            #pragma unroll
            for (int q = 0; q < 4; q++) acc[i][j][q] = 0.0f;

    stage(0, 0);
    stage(1, 1);

    const int nTiles = kD / 32;   // 64
    for (int c = 0; c < nTiles; c++) {
        CP_WAIT1();
        __syncthreads();
        if (c + 2 < nTiles) stage((c + 2) % 3, c + 2);

        const uint32_t base = smem_u32(sm + (c % 3) * 32768);
        const uint32_t a0b = base, a1b = base + 8192;
        const uint32_t b0b = base + 16384, b1b = base + 24576;

        #pragma unroll
        for (int kk = 0; kk < 2; kk++) {
            uint32_t a0f[2][4], a1f[2][4];
            #pragma unroll
            for (int mt = 0; mt < 2; mt++) {
                int row = wm + mt * 16 + (lane & 15);
                uint32_t off = SMEM_SWIZZLE_64B(row * 64 + kk * 32 + (lane >> 4) * 16);
                LDMATRIX_X4(a0f[mt], a0b + off);
                LDMATRIX_X4(a1f[mt], a1b + off);
            }
            #pragma unroll
            for (int p = 0; p < 4; p++) {
                int nrow = wn + p * 16 + (lane & 15);
                uint32_t boff = SMEM_SWIZZLE_64B(nrow * 64 + kk * 32 + (lane >> 4) * 16);
                uint32_t f0[4], f1[4];
                LDMATRIX_X4(f0, b0b + boff);
                LDMATRIX_X4(f1, b1b + boff);
                MMA16816(acc[0][2 * p],     a0f[0], f0[0], f0[2]);
                MMA16816(acc[1][2 * p],     a0f[1], f0[0], f0[2]);
                MMA16816(acc[0][2 * p + 1], a0f[0], f0[1], f0[3]);
                MMA16816(acc[1][2 * p + 1], a0f[1], f0[1], f0[3]);
                MMA16816(acc[0][2 * p],     a0f[0], f1[0], f1[2]);
                MMA16816(acc[1][2 * p],     a0f[1], f1[0], f1[2]);
                MMA16816(acc[0][2 * p + 1], a0f[0], f1[1], f1[3]);
                MMA16816(acc[1][2 * p + 1], a0f[1], f1[1], f1[3]);
                MMA16816(acc[0][2 * p],     a1f[0], f0[0], f0[2]);
                MMA16816(acc[1][2 * p],     a1f[1], f0[0], f0[2]);
                MMA16816(acc[0][2 * p + 1], a1f[0], f0[1], f0[3]);
                MMA16816(acc[1][2 * p + 1], a1f[1], f0[1], f0[3]);
            }
        }
    }

    #pragma unroll
    for (int mt = 0; mt < 2; mt++) {
        #pragma unroll
        for (int nt = 0; nt < 8; nt++) {
            int r = m0 + wm + mt * 16 + (lane >> 2);
            int col = n0 + wn + nt * 8 + (lane & 3) * 2;
            float2 v0 = make_float2(acc[mt][nt][0], acc[mt][nt][1]);
            float2 v1 = make_float2(acc[mt][nt][2], acc[mt][nt][3]);
            *reinterpret_cast<float2*>(C + (size_t)r * kD + col) = v0;
            *reinterpret_cast<float2*>(C + (size_t)(r + 8) * kD + col) = v1;
        }
    }
}

// Xp GEMM: blockIdx-driven wrapper around the shared tile body.
__global__ __launch_bounds__(256, 2) void gemm_bf16_kernel(
    const __nv_bfloat16* __restrict__ A0, const __nv_bfloat16* __restrict__ A1,
    const __nv_bfloat16* __restrict__ B0, const __nv_bfloat16* __restrict__ B1,
    float* __restrict__ C)
{
    extern __shared__ char sm[];
    gemm_tile_body(A0, A1, B0, B1, C, blockIdx.y * 128, blockIdx.x * 128,
                   sm, threadIdx.x, threadIdx.x >> 5, threadIdx.x & 31);
}

// Y-GEMM tail: drains whatever tiles the scan-time helpers didn't claim.
__global__ __launch_bounds__(256, 2) void gemm_y_tail_kernel(float* __restrict__ ys)
{
    extern __shared__ char sm[];
    const int tid = threadIdx.x;
    __shared__ unsigned s_my;
    while (true) {
        if (tid == 0) s_my = atomicAdd(&g_ytile, 1u);
        __syncthreads();
        unsigned my = s_my;
        __syncthreads();
        if (my >= (unsigned)kYTiles) return;
        gemm_tile_body(g_Hs0 + kBD, g_Hs1 + kBD, g_WoT0, g_WoT1, ys,
                       (int)(my >> 4) * 128, (int)(my & 15) * 128,
                       sm, tid, tid >> 5, tid & 31);
        __syncthreads();
    }
}

// ===========================================================================
// Persistent scan + Y-GEMM work-stealing helpers. 148 CTAs:
//   CTAs 0..127  : R13 scan (epoch-REDG barrier; arrival EVERY step so the
//                  final epoch 128*kT is published for helpers)
//   CTAs 128..147: helpers stealing Y tiles gated on scan epochs
// ===========================================================================
__global__ __launch_bounds__(256, 1) void rnn_scan_mma_kernel(
    const __nv_bfloat16* __restrict__ WhT0,
    const __nv_bfloat16* __restrict__ WhT1,
    float* __restrict__ hfinal_out,
    float* __restrict__ ys)
{
    extern __shared__ char dsm_raw[];
    const uint32_t raw = smem_u32(dsm_raw);
    const uint32_t base = (raw + 1023u) & ~1023u;
    char* dsm = dsm_raw + (base - raw);

    const int tid = threadIdx.x;
    const int wid = tid >> 5;
    const int lane = tid & 31;
    unsigned* cnt = &g_count;

    // ---------------- helper CTAs: steal Y-GEMM tiles ----------------
    if (blockIdx.x >= 128) {
        __shared__ unsigned s_my;
        while (true) {
            unsigned done;
            asm volatile("ld.relaxed.gpu.global.u32 %0, [%1];"
                         : "=r"(done) : "l"(cnt));
            if (done >= 128u * (unsigned)kT) break;   // scan finished; tail kernel drains
            if (tid == 0) s_my = atomicAdd(&g_ytile, 1u);
            __syncthreads();
            unsigned my = s_my;
            __syncthreads();
            if (my >= (unsigned)kYTiles) break;
            const int by = (int)(my >> 4), bx = (int)(my & 15);
            const unsigned need = 1024u * (unsigned)(by + 1); // slots <= 8(by+1)
            if (tid == 0) {
                unsigned v;
                do {
                    asm volatile("ld.relaxed.gpu.global.u32 %0, [%1];"
                                 : "=r"(v) : "l"(cnt));
                } while (v < need);
            }
            __syncthreads();
            asm volatile("fence.acq_rel.gpu;" ::: "memory");
            gemm_tile_body(g_Hs0 + kBD, g_Hs1 + kBD, g_WoT0, g_WoT1, ys,
                           by * 128, bx * 128, dsm, tid, wid, lane);
            __syncthreads();
        }
        return;
    }

    // ---------------- scan CTAs: exact R13 recurrence ----------------
    float* part = reinterpret_cast<float*>(dsm + 131072);
    const int n0 = blockIdx.x * 16;

    {
        const __nv_bfloat16* s0 = WhT0 + (size_t)n0 * kD;
        const __nv_bfloat16* s1 = WhT1 + (size_t)n0 * kD;
        for (int i = tid; i < 4096; i += 256) {
            int row = i >> 8, u = i & 255, ch = u >> 3, c8 = u & 7;
            size_t so = (size_t)row * kD + ch * 64 + c8 * 8;
            uint32_t doff = ch * 2048 + SMEM_SWIZZLE_128B(row * 128 + c8 * 16);
            CP_ASYNC16(base + doff, s0 + so);
            CP_ASYNC16(base + 65536 + doff, s1 + so);
        }
        CP_COMMIT();
        CP_WAIT0();
        __syncthreads();
    }

    uint32_t bh[16][4], bl[16][4];       // 128 regs of resident Wh fragments
    #pragma unroll
    for (int s = 0; s < 16; s++) {
        const int ch = wid * 4 + (s >> 2), kk = s & 3;
        const uint32_t off = ch * 2048 +
            SMEM_SWIZZLE_128B((lane & 15) * 128 + kk * 32 + (lane >> 4) * 16);
        LDMATRIX_X4(bh[s], base + off);
        LDMATRIX_X4(bl[s], base + 65536 + off);
    }
    __syncthreads();   // Wh smem region now reused for h staging

    const int r0 = lane >> 2;
    const int cb = (lane & 3) * 2;
    const int rrow = tid >> 4;
    const int rcol = tid & 15;

    const int ld_row_a = lane >> 2;
    const int ld_row_b = 8 + (lane >> 2);
    const int ld_c8a = (lane & 3) * 2;
    const int ld_c8b = ld_c8a + 1;

    for (int t = 0; t < kT; t++) {
        const __nv_bfloat16* h0p = g_Hs0 + (size_t)t * kBD;
        const __nv_bfloat16* h1p = g_Hs1 + (size_t)t * kBD;

        const float xp = __ldg(g_Xp + (size_t)t * kBD + (size_t)rrow * kD + n0 + rcol);

        #pragma unroll
        for (int g = 0; g < 4; g++) {
            const int ch = wid * 4 + g;
            const int rows[2] = {ld_row_a, ld_row_b};
            const int cs[2] = {ld_c8a, ld_c8b};
            #pragma unroll
            for (int ri = 0; ri < 2; ri++) {
                #pragma unroll
                for (int ci = 0; ci < 2; ci++) {
                    const int row = rows[ri], c8 = cs[ci];
                    size_t so = (size_t)row * kD + ch * 64 + c8 * 8;
                    uint32_t doff = ch * 2048 + SMEM_SWIZZLE_128B(row * 128 + c8 * 16);
                    CP_ASYNC16(base + doff, h0p + so);
                    CP_ASYNC16(base + 65536 + doff, h1p + so);
                }
            }
            CP_COMMIT();
        }

        float acc[2][4];
        #pragma unroll
        for (int p = 0; p < 2; p++)
            #pragma unroll
            for (int q = 0; q < 4; q++) acc[p][q] = 0.0f;

        #define SCAN_GROUP(gc)                                                   \
        {                                                                        \
            asm volatile("cp.async.wait_group %0;" :: "n"(3 - (gc)) : "memory"); \
            __syncwarp();                                                        \
            const int ch = wid * 4 + (gc);                                       \
            _Pragma("unroll")                                                    \
            for (int kk = 0; kk < 4; kk++) {                                     \
                const int s = (gc) * 4 + kk;                                     \
                const uint32_t off = ch * 2048 +                                 \
                    SMEM_SWIZZLE_128B((lane & 15) * 128 + kk * 32 +              \
                                      (lane >> 4) * 16);                         \
                uint32_t a0[4], a1[4];                                           \
                LDMATRIX_X4(a0, base + off);                                     \
                LDMATRIX_X4(a1, base + 65536 + off);                             \
                MMA16816(acc[0], a0, bh[s][0], bh[s][2]);                        \
                MMA16816(acc[1], a0, bh[s][1], bh[s][3]);                        \
                MMA16816(acc[0], a0, bl[s][0], bl[s][2]);                        \
                MMA16816(acc[1], a0, bl[s][1], bl[s][3]);                        \
                MMA16816(acc[0], a1, bh[s][0], bh[s][2]);                        \
                MMA16816(acc[1], a1, bh[s][1], bh[s][3]);                        \
            }                                                                    \
        }
        SCAN_GROUP(0)
        SCAN_GROUP(1)
        SCAN_GROUP(2)
        SCAN_GROUP(3)
        #undef SCAN_GROUP

        #pragma unroll
        for (int p = 0; p < 2; p++) {
            *reinterpret_cast<float2*>(&part[wid * 256 + r0 * 16 + p * 8 + cb]) =
                make_float2(acc[p][0], acc[p][1]);
            *reinterpret_cast<float2*>(&part[wid * 256 + (r0 + 8) * 16 + p * 8 + cb]) =
                make_float2(acc[p][2], acc[p][3]);
        }
        __syncthreads();

        {
            float s = xp;
            #pragma unroll
            for (int w = 0; w < 8; w++) s += part[w * 256 + tid];
            float h = tanhf(s);
            __nv_bfloat16 hb = __float2bfloat16_rn(h);
            size_t go = (size_t)(t + 1) * kBD + (size_t)rrow * kD + n0 + rcol;
            g_Hs0[go] = hb;
            g_Hs1[go] = __float2bfloat16_rn(h - __bfloat162float(hb));
            if (t == kT - 1)
                hfinal_out[(size_t)rrow * kD + n0 + rcol] = h;
        }

        // arrival EVERY step (helpers need the final epoch); wait only if
        // another step follows
        __syncthreads();
        if (tid == 0) {
            asm volatile("fence.acq_rel.gpu;" ::: "memory");
            asm volatile("red.relaxed.gpu.global.add.u32 [%0], 1;"
                         :: "l"(cnt) : "memory");
            if (t + 1 < kT) {
                const unsigned target = 128u * (unsigned)(t + 1);
                unsigned v;
                do {
                    asm volatile("ld.relaxed.gpu.global.u32 %0, [%1];"
                                 : "=r"(v) : "l"(cnt));
                } while (v < target);
                asm volatile("fence.acq_rel.gpu;" ::: "memory");
            }
        }
        if (t + 1 < kT) __syncthreads();
    }
}

// ===========================================================================
// Launch
// ===========================================================================
extern "C" void kernel_launch(void* const* d_in, const int* in_sizes, int n_in,
                              void* d_out, int out_size)
{
    const float* h0 = (const float*)d_in[0];
    const float* x  = (const float*)d_in[1];
    const float* Wx = (const float*)d_in[2];
    const float* Wh = (const float*)d_in[3];
    const float* Wo = (const float*)d_in[4];

    float* out  = (float*)d_out;
    float* hfin = out;                 // [B, D]
    float* ys   = out + kBD;           // [T, B, D]

    float* Xp;
    __nv_bfloat16 *Hs0, *Hs1, *Xs0, *Xs1, *WxT0, *WxT1, *WoT0, *WoT1, *WhT0, *WhT1;
    cudaGetSymbolAddress((void**)&Xp,   g_Xp);
    cudaGetSymbolAddress((void**)&Hs0,  g_Hs0);
    cudaGetSymbolAddress((void**)&Hs1,  g_Hs1);
    cudaGetSymbolAddress((void**)&Xs0,  g_Xs0);
    cudaGetSymbolAddress((void**)&Xs1,  g_Xs1);
    cudaGetSymbolAddress((void**)&WxT0, g_WxT0);
    cudaGetSymbolAddress((void**)&WxT1, g_WxT1);
    cudaGetSymbolAddress((void**)&WoT0, g_WoT0);
    cudaGetSymbolAddress((void**)&WoT1, g_WoT1);
    cudaGetSymbolAddress((void**)&WhT0, g_WhT0);
    cudaGetSymbolAddress((void**)&WhT1, g_WhT1);

    const int gemm_smem = 3 * 32768;                 // 96 KB
    const int scan_smem = 131072 + 8192 + 1024;      // 140 KB
    cudaFuncSetAttribute(gemm_bf16_kernel,
                         cudaFuncAttributeMaxDynamicSharedMemorySize, gemm_smem);
    cudaFuncSetAttribute(gemm_y_tail_kernel,
                         cudaFuncAttributeMaxDynamicSharedMemorySize, gemm_smem);
    cudaFuncSetAttribute(rnn_scan_mma_kernel,
                         cudaFuncAttributeMaxDynamicSharedMemorySize, scan_smem);

    // prep: weights transpose+split; counters reset
    dim3 prep_grid(kD / 32, kD / 32, 3), prep_blk(32, 32);
    prep_wT3_kernel<<<prep_grid, prep_blk>>>(Wx, Wh, Wo,
                                             WxT0, WxT1, WhT0, WhT1, WoT0, WoT1);

    // split x and h0
    const int n4x = kM * kD / 4;
    const int n4h = kBD / 4;
    const int nsplit = n4x + n4h;
    split2_kernel<<<(nsplit + 255) / 256, 256>>>(x, Xs0, Xs1, n4x,
                                                 h0, Hs0, Hs1, n4h);

    dim3 gemm_grid(kD / 128, kM / 128);   // (16, 64)

    // Xp = X @ Wx
    gemm_bf16_kernel<<<gemm_grid, 256, gemm_smem>>>(Xs0, Xs1, WxT0, WxT1, Xp);

    // scan (CTAs 0..127) + Y-GEMM work-stealing helpers (CTAs 128..147)
    rnn_scan_mma_kernel<<<148, 256, scan_smem>>>(WhT0, WhT1, hfin, ys);

    // drain remaining Y tiles at full chip width
    gemm_y_tail_kernel<<<1024, 256, gemm_smem>>>(ys);
}

// round 17
// speedup vs baseline: 1.3050x; 1.0119x over previous
#include <cuda_runtime.h>
#include <cuda_bf16.h>
#include <math.h>
#include <stdint.h>

static constexpr int kT = 512;
static constexpr int kB = 16;
static constexpr int kD = 2048;
static constexpr int kBD = kB * kD;          // 32768
static constexpr int kM = kT * kB;           // 8192 rows in big GEMMs
static constexpr int kYTiles = (kM / 128) * (kD / 128);   // 1024 Y-GEMM tiles

// Scratch (device globals; no allocation allowed)
__device__ float g_Xp[kT * kBD];                 // X @ Wx   [T*B, D]
__device__ __nv_bfloat16 g_Hs0[(kT + 1) * kBD]; // h bf16 hi; slot t = h_{t-1}
__device__ __nv_bfloat16 g_Hs1[(kT + 1) * kBD]; // h bf16 lo
__device__ __nv_bfloat16 g_Xs0[kM * kD];         // x bf16 hi
__device__ __nv_bfloat16 g_Xs1[kM * kD];         // x bf16 lo
__device__ __nv_bfloat16 g_WxT0[kD * kD];        // W^T splits, [N][K]
__device__ __nv_bfloat16 g_WxT1[kD * kD];
__device__ __nv_bfloat16 g_WoT0[kD * kD];
__device__ __nv_bfloat16 g_WoT1[kD * kD];
__device__ __nv_bfloat16 g_WhT0[kD * kD];
__device__ __nv_bfloat16 g_WhT1[kD * kD];
__device__ unsigned g_count = 0;                 // scan epoch counter
__device__ unsigned g_ytile = 0;                 // Y-GEMM tile work queue

// ===========================================================================
// PTX helpers — base sm_103 ISA only (no 'a'-gated features)
// ===========================================================================
__device__ __forceinline__ uint32_t smem_u32(const void* p) {
    uint32_t a;
    asm("{ .reg .u64 t; cvta.to.shared.u64 t, %1; cvt.u32.u64 %0, t; }"
        : "=r"(a) : "l"(p));
    return a;
}
#define CP_ASYNC16(dst, src) \
    asm volatile("cp.async.cg.shared.global [%0], [%1], 16;" \
                 :: "r"(dst), "l"(src) : "memory")
#define CP_COMMIT() asm volatile("cp.async.commit_group;" ::: "memory")
#define CP_WAIT1()  asm volatile("cp.async.wait_group 1;" ::: "memory")
#define CP_WAIT0()  asm volatile("cp.async.wait_group 0;" ::: "memory")

#define LDMATRIX_X4(r, addr) \
    asm volatile("ldmatrix.sync.aligned.m8n8.x4.shared.b16 {%0,%1,%2,%3}, [%4];" \
        : "=r"((r)[0]), "=r"((r)[1]), "=r"((r)[2]), "=r"((r)[3]) : "r"(addr))

#define MMA16816(d, a, b0, b1) \
    asm volatile("mma.sync.aligned.m16n8k16.row.col.f32.bf16.bf16.f32 " \
        "{%0,%1,%2,%3}, {%4,%5,%6,%7}, {%8,%9}, {%0,%1,%2,%3};" \
        : "+f"((d)[0]), "+f"((d)[1]), "+f"((d)[2]), "+f"((d)[3]) \
        : "r"((a)[0]), "r"((a)[1]), "r"((a)[2]), "r"((a)[3]), "r"(b0), "r"(b1))

#define SMEM_SWIZZLE_128B(x) ((x) ^ (((x) >> 3) & 0x70))
#define SMEM_SWIZZLE_64B(x)  ((x) ^ (((x) >> 3) & 0x30))

__device__ __forceinline__ unsigned pack_bf2(__nv_bfloat16 a, __nv_bfloat16 b) {
    __nv_bfloat162 h = __halves2bfloat162(a, b);
    return *reinterpret_cast<unsigned*>(&h);
}

// ===========================================================================
// Fused prep: transpose+split ALL THREE weights; zero epoch + work counters.
// ===========================================================================
__global__ void prep_wT3_kernel(const float* __restrict__ Wx,
                                const float* __restrict__ Wh,
                                const float* __restrict__ Wo,
                                __nv_bfloat16* __restrict__ WxT0,
                                __nv_bfloat16* __restrict__ WxT1,
                                __nv_bfloat16* __restrict__ WhT0,
                                __nv_bfloat16* __restrict__ WhT1,
                                __nv_bfloat16* __restrict__ WoT0,
                                __nv_bfloat16* __restrict__ WoT1)
{
    const float* W;
    __nv_bfloat16 *T0, *T1;
    if (blockIdx.z == 0)      { W = Wx; T0 = WxT0; T1 = WxT1; }
    else if (blockIdx.z == 1) { W = Wh; T0 = WhT0; T1 = WhT1; }
    else                      { W = Wo; T0 = WoT0; T1 = WoT1; }

    __shared__ float tile[32][33];
    const int n0 = blockIdx.x * 32, k0 = blockIdx.y * 32;
    const int tx = threadIdx.x, ty = threadIdx.y;
    tile[ty][tx] = W[(size_t)(k0 + ty) * kD + n0 + tx];
    __syncthreads();
    float v = tile[tx][ty];                       // = W[k0+tx][n0+ty]
    __nv_bfloat16 b0 = __float2bfloat16_rn(v);
    float r = v - __bfloat162float(b0);
    __nv_bfloat16 b1 = __float2bfloat16_rn(r);
    size_t o = (size_t)(n0 + ty) * kD + k0 + tx;  // T[n][k]
    T0[o] = b0;
    T1[o] = b1;

    if (blockIdx.x == 0 && blockIdx.y == 0 && blockIdx.z == 0 &&
        tx == 0 && ty == 0) {
        g_count = 0;
        g_ytile = 0;
    }
}

// Fused fp32 -> bf16 hi/lo split for x AND h0 in one launch.
__global__ void split2_kernel(const float* __restrict__ x,
                              __nv_bfloat16* __restrict__ xo0,
                              __nv_bfloat16* __restrict__ xo1, int n4x,
                              const float* __restrict__ h,
                              __nv_bfloat16* __restrict__ ho0,
                              __nv_bfloat16* __restrict__ ho1, int n4h)
{
    int i = blockIdx.x * blockDim.x + threadIdx.x;
    const float* in;
    __nv_bfloat16 *o0, *o1;
    int idx;
    if (i < n4x) { in = x; o0 = xo0; o1 = xo1; idx = i; }
    else {
        idx = i - n4x;
        if (idx >= n4h) return;
        in = h; o0 = ho0; o1 = ho1;
    }
    float4 v = __ldg(reinterpret_cast<const float4*>(in) + idx);
    __nv_bfloat16 hx = __float2bfloat16_rn(v.x);
    __nv_bfloat16 hy = __float2bfloat16_rn(v.y);
    __nv_bfloat16 hz = __float2bfloat16_rn(v.z);
    __nv_bfloat16 hw = __float2bfloat16_rn(v.w);
    __nv_bfloat16 lx = __float2bfloat16_rn(v.x - __bfloat162float(hx));
    __nv_bfloat16 ly = __float2bfloat16_rn(v.y - __bfloat162float(hy));
    __nv_bfloat16 lz = __float2bfloat16_rn(v.z - __bfloat162float(hz));
    __nv_bfloat16 lw = __float2bfloat16_rn(v.w - __bfloat162float(hw));
    uint2 p0 = make_uint2(pack_bf2(hx, hy), pack_bf2(hz, hw));
    uint2 p1 = make_uint2(pack_bf2(lx, ly), pack_bf2(lz, lw));
    reinterpret_cast<uint2*>(o0)[idx] = p0;
    reinterpret_cast<uint2*>(o1)[idx] = p1;
}

// ===========================================================================
// GEMM v6 tile body (shared by Xp GEMM and all Y-tile stealers)
// ===========================================================================
__device__ __forceinline__ void gemm_tile_body(
    const __nv_bfloat16* __restrict__ A0, const __nv_bfloat16* __restrict__ A1,
    const __nv_bfloat16* __restrict__ B0, const __nv_bfloat16* __restrict__ B1,
    float* __restrict__ C, int m0, int n0, char* sm,
    int tid, int wid, int lane)
{
    const int wm = (wid & 3) * 32;
    const int wn = (wid >> 2) * 64;

    auto stage = [&](int buf, int c) {
        const int k0 = c * 32;
        char* base = sm + buf * 32768;
        const __nv_bfloat16* srcs[4] = {
            A0 + (size_t)m0 * kD + k0, A1 + (size_t)m0 * kD + k0,
            B0 + (size_t)n0 * kD + k0, B1 + (size_t)n0 * kD + k0 };
        #pragma unroll
        for (int tile = 0; tile < 4; tile++) {
            #pragma unroll
            for (int j = 0; j < 2; j++) {
                int lin = tid + j * 256;            // 0..511
                int row = lin >> 2, c16 = lin & 3;  // 16B chunk within 64B row
                const __nv_bfloat16* src = srcs[tile] + (size_t)row * kD + c16 * 8;
                uint32_t dst = smem_u32(base + tile * 8192 +
                                        SMEM_SWIZZLE_64B(row * 64 + c16 * 16));
                CP_ASYNC16(dst, src);
            }
        }
        CP_COMMIT();
    };

    float acc[2][8][4];
    #pragma unroll
    for (int i = 0; i < 2; i++)
        #pragma unroll
        for (int j = 0; j < 8; j++)
            #pragma unroll
            for (int q = 0; q < 4; q++) acc[i][j][q] = 0.0f;

    stage(0, 0);
    stage(1, 1);

    const int nTiles = kD / 32;   // 64
    for (int c = 0; c < nTiles; c++) {
        CP_WAIT1();
        __syncthreads();
        if (c + 2 < nTiles) stage((c + 2) % 3, c + 2);

        const uint32_t base = smem_u32(sm + (c % 3) * 32768);
        const uint32_t a0b = base, a1b = base + 8192;
        const uint32_t b0b = base + 16384, b1b = base + 24576;

        #pragma unroll
        for (int kk = 0; kk < 2; kk++) {
            uint32_t a0f[2][4], a1f[2][4];
            #pragma unroll
            for (int mt = 0; mt < 2; mt++) {
                int row = wm + mt * 16 + (lane & 15);
                uint32_t off = SMEM_SWIZZLE_64B(row * 64 + kk * 32 + (lane >> 4) * 16);
                LDMATRIX_X4(a0f[mt], a0b + off);
                LDMATRIX_X4(a1f[mt], a1b + off);
            }
            #pragma unroll
            for (int p = 0; p < 4; p++) {
                int nrow = wn + p * 16 + (lane & 15);
                uint32_t boff = SMEM_SWIZZLE_64B(nrow * 64 + kk * 32 + (lane >> 4) * 16);
                uint32_t f0[4], f1[4];
                LDMATRIX_X4(f0, b0b + boff);
                LDMATRIX_X4(f1, b1b + boff);
                MMA16816(acc[0][2 * p],     a0f[0], f0[0], f0[2]);
                MMA16816(acc[1][2 * p],     a0f[1], f0[0], f0[2]);
                MMA16816(acc[0][2 * p + 1], a0f[0], f0[1], f0[3]);
                MMA16816(acc[1][2 * p + 1], a0f[1], f0[1], f0[3]);
                MMA16816(acc[0][2 * p],     a0f[0], f1[0], f1[2]);
                MMA16816(acc[1][2 * p],     a0f[1], f1[0], f1[2]);
                MMA16816(acc[0][2 * p + 1], a0f[0], f1[1], f1[3]);
                MMA16816(acc[1][2 * p + 1], a0f[1], f1[1], f1[3]);
                MMA16816(acc[0][2 * p],     a1f[0], f0[0], f0[2]);
                MMA16816(acc[1][2 * p],     a1f[1], f0[0], f0[2]);
                MMA16816(acc[0][2 * p + 1], a1f[0], f0[1], f0[3]);
                MMA16816(acc[1][2 * p + 1], a1f[1], f0[1], f0[3]);
            }
        }
    }

    #pragma unroll
    for (int mt = 0; mt < 2; mt++) {
        #pragma unroll
        for (int nt = 0; nt < 8; nt++) {
            int r = m0 + wm + mt * 16 + (lane >> 2);
            int col = n0 + wn + nt * 8 + (lane & 3) * 2;
            float2 v0 = make_float2(acc[mt][nt][0], acc[mt][nt][1]);
            float2 v1 = make_float2(acc[mt][nt][2], acc[mt][nt][3]);
            *reinterpret_cast<float2*>(C + (size_t)r * kD + col) = v0;
            *reinterpret_cast<float2*>(C + (size_t)(r + 8) * kD + col) = v1;
        }
    }
}

// Xp GEMM: blockIdx-driven wrapper around the shared tile body.
__global__ __launch_bounds__(256, 2) void gemm_bf16_kernel(
    const __nv_bfloat16* __restrict__ A0, const __nv_bfloat16* __restrict__ A1,
    const __nv_bfloat16* __restrict__ B0, const __nv_bfloat16* __restrict__ B1,
    float* __restrict__ C)
{
    extern __shared__ char sm[];
    gemm_tile_body(A0, A1, B0, B1, C, blockIdx.y * 128, blockIdx.x * 128,
                   sm, threadIdx.x, threadIdx.x >> 5, threadIdx.x & 31);
}

// Shared Y-tile steal loop: pop ascending tiles, gate on scan epoch, compute.
// Runs on helper CTAs during the scan AND on all CTAs after the scan.
__device__ __forceinline__ void y_steal_loop(float* __restrict__ ys, char* dsm,
                                             int tid, int wid, int lane,
                                             unsigned* cnt)
{
    __shared__ unsigned s_my;
    while (true) {
        if (tid == 0) s_my = atomicAdd(&g_ytile, 1u);
        __syncthreads();
        unsigned my = s_my;
        __syncthreads();
        if (my >= (unsigned)kYTiles) return;
        const int by = (int)(my >> 4), bx = (int)(my & 15);
        const unsigned need = 1024u * (unsigned)(by + 1); // slots <= 8(by+1)
        if (tid == 0) {
            unsigned v;
            do {
                asm volatile("ld.relaxed.gpu.global.u32 %0, [%1];"
                             : "=r"(v) : "l"(cnt));
            } while (v < need);
        }
        __syncthreads();
        asm volatile("fence.acq_rel.gpu;" ::: "memory");
        gemm_tile_body(g_Hs0 + kBD, g_Hs1 + kBD, g_WoT0, g_WoT1, ys,
                       by * 128, bx * 128, dsm, tid, wid, lane);
        __syncthreads();
    }
}

// ===========================================================================
// Persistent scan + Y-GEMM. 148 CTAs:
//   CTAs 0..127  : R13 scan; after the last step they FALL THROUGH into the
//                  Y-tile steal loop (no separate tail kernel).
//   CTAs 128..147: steal Y tiles for the whole kernel duration.
// Queue drained exactly once; identical tile body -> bit-identical output.
// ===========================================================================
__global__ __launch_bounds__(256, 1) void rnn_scan_mma_kernel(
    const __nv_bfloat16* __restrict__ WhT0,
    const __nv_bfloat16* __restrict__ WhT1,
    float* __restrict__ hfinal_out,
    float* __restrict__ ys)
{
    extern __shared__ char dsm_raw[];
    const uint32_t raw = smem_u32(dsm_raw);
    const uint32_t base = (raw + 1023u) & ~1023u;
    char* dsm = dsm_raw + (base - raw);

    const int tid = threadIdx.x;
    const int wid = tid >> 5;
    const int lane = tid & 31;
    unsigned* cnt = &g_count;

    // ---------------- helper CTAs: steal the whole time ----------------
    if (blockIdx.x >= 128) {
        y_steal_loop(ys, dsm, tid, wid, lane, cnt);
        return;
    }

    // ---------------- scan CTAs: exact R13 recurrence ----------------
    float* part = reinterpret_cast<float*>(dsm + 131072);
    const int n0 = blockIdx.x * 16;

    {
        const __nv_bfloat16* s0 = WhT0 + (size_t)n0 * kD;
        const __nv_bfloat16* s1 = WhT1 + (size_t)n0 * kD;
        for (int i = tid; i < 4096; i += 256) {
            int row = i >> 8, u = i & 255, ch = u >> 3, c8 = u & 7;
            size_t so = (size_t)row * kD + ch * 64 + c8 * 8;
            uint32_t doff = ch * 2048 + SMEM_SWIZZLE_128B(row * 128 + c8 * 16);
            CP_ASYNC16(base + doff, s0 + so);
            CP_ASYNC16(base + 65536 + doff, s1 + so);
        }
        CP_COMMIT();
        CP_WAIT0();
        __syncthreads();
    }

    uint32_t bh[16][4], bl[16][4];       // 128 regs of resident Wh fragments
    #pragma unroll
    for (int s = 0; s < 16; s++) {
        const int ch = wid * 4 + (s >> 2), kk = s & 3;
        const uint32_t off = ch * 2048 +
            SMEM_SWIZZLE_128B((lane & 15) * 128 + kk * 32 + (lane >> 4) * 16);
        LDMATRIX_X4(bh[s], base + off);
        LDMATRIX_X4(bl[s], base + 65536 + off);
    }
    __syncthreads();   // Wh smem region now reused for h staging

    const int r0 = lane >> 2;
    const int cb = (lane & 3) * 2;
    const int rrow = tid >> 4;
    const int rcol = tid & 15;

    const int ld_row_a = lane >> 2;
    const int ld_row_b = 8 + (lane >> 2);
    const int ld_c8a = (lane & 3) * 2;
    const int ld_c8b = ld_c8a + 1;

    for (int t = 0; t < kT; t++) {
        const __nv_bfloat16* h0p = g_Hs0 + (size_t)t * kBD;
        const __nv_bfloat16* h1p = g_Hs1 + (size_t)t * kBD;

        const float xp = __ldg(g_Xp + (size_t)t * kBD + (size_t)rrow * kD + n0 + rcol);

        #pragma unroll
        for (int g = 0; g < 4; g++) {
            const int ch = wid * 4 + g;
            const int rows[2] = {ld_row_a, ld_row_b};
            const int cs[2] = {ld_c8a, ld_c8b};
            #pragma unroll
            for (int ri = 0; ri < 2; ri++) {
                #pragma unroll
                for (int ci = 0; ci < 2; ci++) {
                    const int row = rows[ri], c8 = cs[ci];
                    size_t so = (size_t)row * kD + ch * 64 + c8 * 8;
                    uint32_t doff = ch * 2048 + SMEM_SWIZZLE_128B(row * 128 + c8 * 16);
                    CP_ASYNC16(base + doff, h0p + so);
                    CP_ASYNC16(base + 65536 + doff, h1p + so);
                }
            }
            CP_COMMIT();
        }

        float acc[2][4];
        #pragma unroll
        for (int p = 0; p < 2; p++)
            #pragma unroll
            for (int q = 0; q < 4; q++) acc[p][q] = 0.0f;

        #define SCAN_GROUP(gc)                                                   \
        {                                                                        \
            asm volatile("cp.async.wait_group %0;" :: "n"(3 - (gc)) : "memory"); \
            __syncwarp();                                                        \
            const int ch = wid * 4 + (gc);                                       \
            _Pragma("unroll")                                                    \
            for (int kk = 0; kk < 4; kk++) {                                     \
                const int s = (gc) * 4 + kk;                                     \
                const uint32_t off = ch * 2048 +                                 \
                    SMEM_SWIZZLE_128B((lane & 15) * 128 + kk * 32 +              \
                                      (lane >> 4) * 16);                         \
                uint32_t a0[4], a1[4];                                           \
                LDMATRIX_X4(a0, base + off);                                     \
                LDMATRIX_X4(a1, base + 65536 + off);                             \
                MMA16816(acc[0], a0, bh[s][0], bh[s][2]);                        \
                MMA16816(acc[1], a0, bh[s][1], bh[s][3]);                        \
                MMA16816(acc[0], a0, bl[s][0], bl[s][2]);                        \
                MMA16816(acc[1], a0, bl[s][1], bl[s][3]);                        \
                MMA16816(acc[0], a1, bh[s][0], bh[s][2]);                        \
                MMA16816(acc[1], a1, bh[s][1], bh[s][3]);                        \
            }                                                                    \
        }
        SCAN_GROUP(0)
        SCAN_GROUP(1)
        SCAN_GROUP(2)
        SCAN_GROUP(3)
        #undef SCAN_GROUP

        #pragma unroll
        for (int p = 0; p < 2; p++) {
            *reinterpret_cast<float2*>(&part[wid * 256 + r0 * 16 + p * 8 + cb]) =
                make_float2(acc[p][0], acc[p][1]);
            *reinterpret_cast<float2*>(&part[wid * 256 + (r0 + 8) * 16 + p * 8 + cb]) =
                make_float2(acc[p][2], acc[p][3]);
        }
        __syncthreads();

        {
            float s = xp;
            #pragma unroll
            for (int w = 0; w < 8; w++) s += part[w * 256 + tid];
            float h = tanhf(s);
            __nv_bfloat16 hb = __float2bfloat16_rn(h);
            size_t go = (size_t)(t + 1) * kBD + (size_t)rrow * kD + n0 + rcol;
            g_Hs0[go] = hb;
            g_Hs1[go] = __float2bfloat16_rn(h - __bfloat162float(hb));
            if (t == kT - 1)
                hfinal_out[(size_t)rrow * kD + n0 + rcol] = h;
        }

        // arrival EVERY step (stealers gate on epochs); wait only mid-scan
        __syncthreads();
        if (tid == 0) {
            asm volatile("fence.acq_rel.gpu;" ::: "memory");
            asm volatile("red.relaxed.gpu.global.add.u32 [%0], 1;"
                         :: "l"(cnt) : "memory");
            if (t + 1 < kT) {
                const unsigned target = 128u * (unsigned)(t + 1);
                unsigned v;
                do {
                    asm volatile("ld.relaxed.gpu.global.u32 %0, [%1];"
                                 : "=r"(v) : "l"(cnt));
                } while (v < target);
                asm volatile("fence.acq_rel.gpu;" ::: "memory");
            }
        }
        __syncthreads();
    }

    // scan done: join the Y-tile steal loop (gates pass immediately)
    y_steal_loop(ys, dsm, tid, wid, lane, cnt);
}

// ===========================================================================
// Launch
// ===========================================================================
extern "C" void kernel_launch(void* const* d_in, const int* in_sizes, int n_in,
                              void* d_out, int out_size)
{
    const float* h0 = (const float*)d_in[0];
    const float* x  = (const float*)d_in[1];
    const float* Wx = (const float*)d_in[2];
    const float* Wh = (const float*)d_in[3];
    const float* Wo = (const float*)d_in[4];

    float* out  = (float*)d_out;
    float* hfin = out;                 // [B, D]
    float* ys   = out + kBD;           // [T, B, D]

    float* Xp;
    __nv_bfloat16 *Hs0, *Hs1, *Xs0, *Xs1, *WxT0, *WxT1, *WoT0, *WoT1, *WhT0, *WhT1;
    cudaGetSymbolAddress((void**)&Xp,   g_Xp);
    cudaGetSymbolAddress((void**)&Hs0,  g_Hs0);
    cudaGetSymbolAddress((void**)&Hs1,  g_Hs1);
    cudaGetSymbolAddress((void**)&Xs0,  g_Xs0);
    cudaGetSymbolAddress((void**)&Xs1,  g_Xs1);
    cudaGetSymbolAddress((void**)&WxT0, g_WxT0);
    cudaGetSymbolAddress((void**)&WxT1, g_WxT1);
    cudaGetSymbolAddress((void**)&WoT0, g_WoT0);
    cudaGetSymbolAddress((void**)&WoT1, g_WoT1);
    cudaGetSymbolAddress((void**)&WhT0, g_WhT0);
    cudaGetSymbolAddress((void**)&WhT1, g_WhT1);

    const int gemm_smem = 3 * 32768;                 // 96 KB
    const int scan_smem = 131072 + 8192 + 1024;      // 140 KB
    cudaFuncSetAttribute(gemm_bf16_kernel,
                         cudaFuncAttributeMaxDynamicSharedMemorySize, gemm_smem);
    cudaFuncSetAttribute(rnn_scan_mma_kernel,
                         cudaFuncAttributeMaxDynamicSharedMemorySize, scan_smem);

    // prep: weights transpose+split; counters reset
    dim3 prep_grid(kD / 32, kD / 32, 3), prep_blk(32, 32);
    prep_wT3_kernel<<<prep_grid, prep_blk>>>(Wx, Wh, Wo,
                                             WxT0, WxT1, WhT0, WhT1, WoT0, WoT1);

    // split x and h0
    const int n4x = kM * kD / 4;
    const int n4h = kBD / 4;
    const int nsplit = n4x + n4h;
    split2_kernel<<<(nsplit + 255) / 256, 256>>>(x, Xs0, Xs1, n4x,
                                                 h0, Hs0, Hs1, n4h);

    dim3 gemm_grid(kD / 128, kM / 128);   // (16, 64)

    // Xp = X @ Wx
    gemm_bf16_kernel<<<gemm_grid, 256, gemm_smem>>>(Xs0, Xs1, WxT0, WxT1, Xp);

    // scan + integrated Y GEMM (helpers during, everyone after)
    rnn_scan_mma_kernel<<<148, 256, scan_smem>>>(WhT0, WhT1, hfin, ys);
}